// round 15
// baseline (speedup 1.0000x reference)
#include <cuda_runtime.h>
#include <math.h>

#define BB 4
#define NN 65536
#define KK 16
#define HH 64
#define TPB 128
#define NPTS (BB * NN)
#define NTILES (NPTS / TPB)      // 2048
#define GRID_MAIN 456            // ~3 blocks/SM persistent

// Scratch: xyz repacked as float4 per point (w unused). 4 MB.
__device__ float4 g_xyz4[NPTS];
__device__ int g_idx_is64;

// ---- packed f32x2 helpers (sm_10x; ptxas never auto-fuses) ----
__device__ __forceinline__ unsigned long long pk2(float lo, float hi) {
    unsigned long long d;
    asm("mov.b64 %0, {%1, %2};" : "=l"(d) : "f"(lo), "f"(hi));
    return d;
}
__device__ __forceinline__ unsigned long long ffma2(
    unsigned long long a, unsigned long long b, unsigned long long c) {
    unsigned long long d;
    asm("fma.rn.f32x2 %0, %1, %2, %3;" : "=l"(d) : "l"(a), "l"(b), "l"(c));
    return d;
}
__device__ __forceinline__ void upk2(unsigned long long v, float& lo, float& hi) {
    asm("mov.b64 {%0, %1}, %2;" : "=f"(lo), "=f"(hi) : "l"(v));
}

// Transpose pos (B,3,N) -> g_xyz4[b*N+n] = {x,y,z,0}, coalesced per coord.
// Warp 0 of block 0 also detects idx dtype (int64 values < 65536 have all-zero
// odd 32-bit words; int32 words are random indices, P[false positive] ~ 2^-1024).
__global__ void transpose_pos_kernel(const float* __restrict__ pos,
                                     const unsigned* __restrict__ idxw) {
    if (blockIdx.x == 0 && threadIdx.x < 32) {
        unsigned v = idxw[4 * threadIdx.x + 1] | idxw[4 * threadIdx.x + 3];
        unsigned any = __ballot_sync(0xffffffffu, v != 0u);
        if (threadIdx.x == 0) g_idx_is64 = (any == 0u) ? 1 : 0;
    }
    int t = blockIdx.x * blockDim.x + threadIdx.x;
    if (t >= NPTS) return;
    int b = t >> 16;
    int n = t & (NN - 1);
    const float* p = pos + (size_t)b * 3 * NN;
    float4 v;
    v.x = p[n];
    v.y = p[NN + n];
    v.z = p[2 * NN + n];
    v.w = 0.0f;
    g_xyz4[t] = v;
}

// Phase 2: matvec + relu for one 128-point tile from smem feats.
// 16 consecutive lanes cover one point's 64 channels -> warp stores 512B
// contiguous (4 L1 wavefronts).
__device__ __forceinline__ void phase2(
    const float (*fs)[10], long tile_base, int c, int sub,
    const unsigned long long* Wxy, const unsigned long long* Wzw,
    unsigned long long Bxy, unsigned long long Bzw, float* out)
{
#pragma unroll
    for (int it = 0; it < 16; it++) {
        int pl = it * 8 + sub;
        unsigned long long axy = Bxy, azw = Bzw;
#pragma unroll
        for (int j = 0; j < 10; j++) {
            float f = fs[pl][j];               // broadcast LDS
            unsigned long long ff = pk2(f, f); // ALU pipe
            axy = ffma2(ff, Wxy[j], axy);
            azw = ffma2(ff, Wzw[j], azw);
        }
        float4 acc;
        upk2(axy, acc.x, acc.y);
        upk2(azw, acc.z, acc.w);
        acc.x = fmaxf(acc.x, 0.0f);
        acc.y = fmaxf(acc.y, 0.0f);
        acc.z = fmaxf(acc.z, 0.0f);
        acc.w = fmaxf(acc.w, 0.0f);
        ((float4*)(out + (tile_base + pl) * HH))[c] = acc;
    }
}

__global__ __launch_bounds__(TPB, 3) void point_embed_kernel(
    const void* __restrict__ idxv,
    const float* __restrict__ dist,
    const float* __restrict__ W,
    const float* __restrict__ bias,
    float* __restrict__ out)
{
    __shared__ float feat_s[2][TPB][10];

    int tid = threadIdx.x;
    int c   = tid & 15;
    int sub = tid >> 4;

    // Persistent W hoist (packed f32x2 pairs; channel group fixed per thread).
    unsigned long long Wxy[10], Wzw[10];
#pragma unroll
    for (int j = 0; j < 10; j++) {
        float4 w = ((const float4*)W)[j * 16 + c];
        Wxy[j] = pk2(w.x, w.y);
        Wzw[j] = pk2(w.z, w.w);
    }
    float4 bb = ((const float4*)bias)[c];
    unsigned long long Bxy = pk2(bb.x, bb.y);
    unsigned long long Bzw = pk2(bb.z, bb.w);

    bool is64 = (g_idx_is64 != 0);
    int buf = 0;
    long prev_base = 0;
    bool prev_valid = false;

    for (int tile = blockIdx.x; tile < NTILES; tile += GRID_MAIN) {
        int t = tile * TPB + tid;
        int base = (t >> 16) << 16;

        // ---- issue: idx loads + 16 gathers + dist loads (all in flight) ----
        int id[KK];
        if (is64) {
            const int4* q = (const int4*)((const char*)idxv + (size_t)t * (KK * 8));
#pragma unroll
            for (int i = 0; i < 8; i++) {
                int4 v = q[i];
                id[2 * i + 0] = v.x & (NN - 1);
                id[2 * i + 1] = v.z & (NN - 1);
            }
        } else {
            const int4* q = (const int4*)((const char*)idxv + (size_t)t * (KK * 4));
#pragma unroll
            for (int i = 0; i < 4; i++) {
                int4 v = q[i];
                id[4 * i + 0] = v.x & (NN - 1);
                id[4 * i + 1] = v.y & (NN - 1);
                id[4 * i + 2] = v.z & (NN - 1);
                id[4 * i + 3] = v.w & (NN - 1);
            }
        }
        float4 p = g_xyz4[t];
        float4 arr[KK];
#pragma unroll
        for (int k = 0; k < KK; k++)
            arr[k] = g_xyz4[base + id[k]];     // 16 LDG.128 outstanding

        const float4* d4 = (const float4*)(dist + (size_t)t * KK);
        float4 da = d4[0], db = d4[1], dc = d4[2], dd = d4[3];

        // ---- overlap: previous tile's matvec runs under gather latency ----
        if (prev_valid)
            phase2(feat_s[buf ^ 1], prev_base, c, sub, Wxy, Wzw, Bxy, Bzw, out);

        // ---- consume gathers ----
        float mnx = -INFINITY, mny = -INFINITY, mnz = -INFINITY;
        float mdx = -INFINITY, mdy = -INFINITY, mdz = -INFINITY;
#pragma unroll
        for (int k = 0; k < KK; k++) {
            float4 q = arr[k];
            mnx = fmaxf(mnx, q.x);
            mny = fmaxf(mny, q.y);
            mnz = fmaxf(mnz, q.z);
            mdx = fmaxf(mdx, p.x - q.x);
            mdy = fmaxf(mdy, p.y - q.y);
            mdz = fmaxf(mdz, p.z - q.z);
        }
        float m0 = fmaxf(fmaxf(da.x, da.y), fmaxf(da.z, da.w));
        float m1 = fmaxf(fmaxf(db.x, db.y), fmaxf(db.z, db.w));
        float m2 = fmaxf(fmaxf(dc.x, dc.y), fmaxf(dc.z, dc.w));
        float m3 = fmaxf(fmaxf(dd.x, dd.y), fmaxf(dd.z, dd.w));
        float md = fmaxf(fmaxf(m0, m1), fmaxf(m2, m3));

        feat_s[buf][tid][0] = p.x;  feat_s[buf][tid][1] = p.y;
        feat_s[buf][tid][2] = p.z;  feat_s[buf][tid][3] = mnx;
        feat_s[buf][tid][4] = mny;  feat_s[buf][tid][5] = mnz;
        feat_s[buf][tid][6] = mdx;  feat_s[buf][tid][7] = mdy;
        feat_s[buf][tid][8] = mdz;  feat_s[buf][tid][9] = md;

        __syncthreads();

        prev_base = (long)tile * TPB;
        prev_valid = true;
        buf ^= 1;
    }

    // drain: last tile's matvec
    if (prev_valid)
        phase2(feat_s[buf ^ 1], prev_base, c, sub, Wxy, Wzw, Bxy, Bzw, out);
}

extern "C" void kernel_launch(void* const* d_in, const int* in_sizes, int n_in,
                              void* d_out, int out_size) {
    const float* pos  = (const float*)d_in[0];
    const void*  idx  = d_in[1];
    const float* dist = (const float*)d_in[2];
    const float* W    = (const float*)d_in[3];
    const float* bias = (const float*)d_in[4];
    float* out = (float*)d_out;

    transpose_pos_kernel<<<(NPTS + 255) / 256, 256>>>(pos, (const unsigned*)idx);
    point_embed_kernel<<<GRID_MAIN, TPB>>>(idx, dist, W, bias, out);
}